// round 13
// baseline (speedup 1.0000x reference)
#include <cuda_runtime.h>

// Sparsemax attention, fp32.  B=8, L=S=1024, H=16, E=D=64.
// out[b,l,h,d] = sum_s sparsemax_s( 0.125 * sum_e q[b,l,h,e]*k[b,s,h,e] ) * v[b,s,h,d]
//
// v2: 2 CTAs/SM (16 rows/CTA, 102KB smem), packed fma.rn.f32x2 along the
// reduction axis (no pack instructions), padded conflict-free LDS.128 feeds.

#define NB 8
#define NL 1024
#define NS 1024
#define NH 16
#define NE 64
#define ND 64
#define MROWS 16     // L rows per CTA
#define TSZ   128    // S tile
#define NT    256    // threads per CTA
#define KPITCH 68    // sK row pitch in floats (17 x 16B units, odd -> conflict-free LDS.128)
#define VPITCH 132   // sVT row pitch in floats (33 x 16B units, odd -> conflict-free LDS.128)

// smem floats: Q + K/VT region (aliased) + scores + tau
#define SMEM_FLOATS (MROWS*NE + TSZ*KPITCH + MROWS*NS + MROWS)
#define SMEM_BYTES  (SMEM_FLOATS * 4)

typedef unsigned long long ull;
union F2U { ull u; float2 f; };

__device__ __forceinline__ void fma2(ull& d, ull a, ull b) {
    asm("fma.rn.f32x2 %0, %1, %2, %0;" : "+l"(d) : "l"(a), "l"(b));
}

__device__ __forceinline__ float warp_sum_f(float v) {
#pragma unroll
    for (int o = 16; o > 0; o >>= 1) v += __shfl_xor_sync(0xffffffffu, v, o);
    return v;
}
__device__ __forceinline__ int warp_sum_i(int v) {
#pragma unroll
    for (int o = 16; o > 0; o >>= 1) v += __shfl_xor_sync(0xffffffffu, v, o);
    return v;
}

__global__ void __launch_bounds__(NT, 2)
sparsemax_attn_kernel(const float* __restrict__ Q, const float* __restrict__ K,
                      const float* __restrict__ V, float* __restrict__ O)
{
    extern __shared__ float sm[];
    float* sQ   = sm;                       // [MROWS][NE]           4 KB
    float* sK   = sm + MROWS * NE;          // [TSZ][KPITCH]        34 KB  (aliased: sVT [ND][VPITCH])
    float* sS   = sK + TSZ * KPITCH;        // [MROWS][NS]          64 KB
    float* sTau = sS + MROWS * NS;          // [MROWS]
    float* sVT  = sK;                       // alias

    const int ltile = blockIdx.x;           // 0..63
    const int h     = blockIdx.y;
    const int b     = blockIdx.z;
    const int l0    = ltile * MROWS;
    const int tid   = threadIdx.x;
    const int tx    = tid & 31;
    const int ty    = tid >> 5;             // warp 0..7
    const int rg    = ty & 3;               // row group: rows 4*rg..4*rg+3
    const int cg    = ty >> 2;              // col group (0/1)

    // ---------------- load Q tile [MROWS][NE] (1 float4 per thread) ----------------
    {
        int row = tid >> 4;                 // / (NE/4)
        int eq  = tid & 15;
        reinterpret_cast<float4*>(sQ)[row * (NE / 4) + eq] =
            reinterpret_cast<const float4*>(Q)
                [((size_t)((b * NL + l0 + row) * NH + h)) * (NE / 4) + eq];
    }

    const float scale = 0.125f;

    // ---------------- QK^T: scores -> sS ----------------
    // per-thread micro-tile: 4 rows x 2 cols, packed over e (reduction)
    const int c0 = cg * 64 + tx;            // tile-local cols c0, c0+32
    for (int st = 0; st < NS / TSZ; ++st) {
        const int s0 = st * TSZ;
        __syncthreads();                    // protect sK vs prior readers
        {
            // 8 float4 per thread, coalesced LDG, conflict-free STS.128
#pragma unroll
            for (int k = 0; k < 8; ++k) {
                int idx = tid + k * NT;
                int sl = idx >> 4;
                int eq = idx & 15;
                float4 kv = reinterpret_cast<const float4*>(
                    K + ((size_t)((b * NS + s0 + sl) * NH + h)) * NE)[eq];
                *reinterpret_cast<float4*>(&sK[sl * KPITCH + eq * 4]) = kv;
            }
        }
        __syncthreads();

        ull acc[4][2];
#pragma unroll
        for (int r = 0; r < 4; r++) { acc[r][0] = 0ull; acc[r][1] = 0ull; }

#pragma unroll 4
        for (int e = 0; e < NE; e += 4) {
            ulonglong2 b0 = *reinterpret_cast<const ulonglong2*>(&sK[c0 * KPITCH + e]);
            ulonglong2 b1 = *reinterpret_cast<const ulonglong2*>(&sK[(c0 + 32) * KPITCH + e]);
#pragma unroll
            for (int r = 0; r < 4; r++) {
                ulonglong2 a = *reinterpret_cast<const ulonglong2*>(&sQ[(rg * 4 + r) * NE + e]);
                fma2(acc[r][0], a.x, b0.x);
                fma2(acc[r][0], a.y, b0.y);
                fma2(acc[r][1], a.x, b1.x);
                fma2(acc[r][1], a.y, b1.y);
            }
        }

#pragma unroll
        for (int r = 0; r < 4; r++) {
            F2U u0, u1; u0.u = acc[r][0]; u1.u = acc[r][1];
            sS[(rg * 4 + r) * NS + s0 + c0]      = (u0.f.x + u0.f.y) * scale;
            sS[(rg * 4 + r) * NS + s0 + c0 + 32] = (u1.f.x + u1.f.y) * scale;
        }
    }
    __syncthreads();

    // ---------------- sparsemax tau per row (Michelot, exact) ----------------
    // warp ty handles rows 2*ty, 2*ty+1; row cached in 32 regs/lane (LDS.128)
    {
#pragma unroll
        for (int rr = 0; rr < 2; ++rr) {
            const int r = ty * 2 + rr;
            const float* row = sS + r * NS;
            float z[32];
#pragma unroll
            for (int k = 0; k < 8; k++) {
                float4 v = *reinterpret_cast<const float4*>(&row[4 * tx + 128 * k]);
                z[4 * k + 0] = v.x; z[4 * k + 1] = v.y;
                z[4 * k + 2] = v.z; z[4 * k + 3] = v.w;
            }
            float s = 0.f;
#pragma unroll
            for (int k = 0; k < 32; k++) s += z[k];
            s = warp_sum_f(s);
            float tau = (s - 1.0f) * (1.0f / (float)NS);
            int prev = NS;
            for (int iter = 0; iter < 64; ++iter) {
                float ss = 0.f; int c = 0;
#pragma unroll
                for (int k = 0; k < 32; k++) {
                    float v = z[k];
                    if (v > tau) { ss += v; c += 1; }
                }
                ss = warp_sum_f(ss);
                c  = warp_sum_i(c);
                tau = (ss - 1.0f) / (float)c;
                if (c == prev) break;
                prev = c;
            }
            if (tx == 0) sTau[r] = tau;
        }
    }
    __syncthreads();

    // ---------------- scores -> A in place ----------------
    {
        float4* sS4 = reinterpret_cast<float4*>(sS);
#pragma unroll
        for (int k = 0; k < MROWS * NS / 4 / NT; ++k) {
            int i = tid + k * NT;
            int r = i >> 8;                 // / (NS/4)
            float tau = sTau[r];
            float4 v = sS4[i];
            v.x = fmaxf(v.x - tau, 0.f);
            v.y = fmaxf(v.y - tau, 0.f);
            v.z = fmaxf(v.z - tau, 0.f);
            v.w = fmaxf(v.w - tau, 0.f);
            sS4[i] = v;
        }
    }

    // ---------------- A @ V (V transposed in smem, packed over s) ----------------
    const int d0 = cg * 32 + tx;            // this thread's d column
    ull oacc[4];
#pragma unroll
    for (int r = 0; r < 4; r++) oacc[r] = 0ull;

    for (int st = 0; st < NS / TSZ; ++st) {
        const int s0 = st * TSZ;
        __syncthreads();                    // protect sVT vs prior readers / convert pass
        {
            // transpose-load V: lanes vary s -> conflict-free STS; scattered LDG (cheap, DRAM idle)
#pragma unroll
            for (int m = 0; m < 8; ++m) {
                int dq = ty + 8 * (m & 1);          // 0..15
                int sl = (m >> 1) * 32 + tx;        // 0..127
                float4 vv = reinterpret_cast<const float4*>(
                    V + ((size_t)((b * NS + s0 + sl) * NH + h)) * ND)[dq];
                sVT[(4 * dq + 0) * VPITCH + sl] = vv.x;
                sVT[(4 * dq + 1) * VPITCH + sl] = vv.y;
                sVT[(4 * dq + 2) * VPITCH + sl] = vv.z;
                sVT[(4 * dq + 3) * VPITCH + sl] = vv.w;
            }
        }
        __syncthreads();

#pragma unroll 8
        for (int s = 0; s < TSZ; s += 4) {
            ulonglong2 bv = *reinterpret_cast<const ulonglong2*>(&sVT[d0 * VPITCH + s]);
#pragma unroll
            for (int r = 0; r < 4; r++) {
                ulonglong2 av = *reinterpret_cast<const ulonglong2*>(
                    &sS[(rg * 4 + r) * NS + s0 + s]);
                fma2(oacc[r], av.x, bv.x);
                fma2(oacc[r], av.y, bv.y);
            }
        }
    }

    // ---------------- write out [b, l, h, d] ----------------
#pragma unroll
    for (int r = 0; r < 4; r++) {
        F2U u; u.u = oacc[r];
        int l = l0 + rg * 4 + r;
        O[((size_t)((b * NL + l) * NH + h)) * ND + d0] = u.f.x + u.f.y;
    }
}

extern "C" void kernel_launch(void* const* d_in, const int* in_sizes, int n_in,
                              void* d_out, int out_size) {
    const float* Q = (const float*)d_in[0];   // queries [B,L,H,E]
    const float* K = (const float*)d_in[1];   // keys    [B,S,H,E]
    const float* V = (const float*)d_in[2];   // values  [B,S,H,D]
    float* O = (float*)d_out;                 // out     [B,L,H,D]

    cudaFuncSetAttribute(sparsemax_attn_kernel,
                         cudaFuncAttributeMaxDynamicSharedMemorySize, SMEM_BYTES);
    dim3 grid(NL / MROWS, NH, NB);
    sparsemax_attn_kernel<<<grid, NT, SMEM_BYTES>>>(Q, K, V, O);
}

// round 16
// speedup vs baseline: 1.9324x; 1.9324x over previous
#include <cuda_runtime.h>
#include <cuda_bf16.h>
#include <cstdint>

// Sparsemax attention, fused, bf16-split mma.sync (HMMA) on sm_103.
// B=8, H=16, L=S=1024, E=D=64, fp32 in/out.

#define B_ 8
#define H_ 16
#define L_ 1024
#define S_ 1024
#define MR 16      // L rows per CTA
#define SB 128     // s block
#define NT 256

// ---- SMEM byte offsets (dynamic) ----
#define APITCH 2064                 // A/score plane row pitch (1032 bf16), 129 units (odd)
#define AHI    0                    // score/A hi plane: 16 x 2064 = 33024
#define ALO    33024                // lo plane
#define WREG   66048                // K or V planes region
#define KVP    144                  // K/V plane pitch bytes (72 bf16), 9 units (odd)
#define WPL    18432                // one K/V plane: 128 x 144
#define QHI    (WREG + 2*WPL)      // 102912
#define QLO    (QHI + 2304)         // Q plane: 16 x 144 = 2304
#define SMEM_BYTES (QLO + 2304)     // 107520

// ---------------- helpers ----------------
__device__ __forceinline__ uint32_t smem_u32(const void* p) {
    uint32_t a;
    asm("{ .reg .u64 t; cvta.to.shared.u64 t, %1; cvt.u32.u64 %0, t; }" : "=r"(a) : "l"(p));
    return a;
}
__device__ __forceinline__ void ldsm_x4(uint32_t* r, uint32_t a) {
    asm volatile("ldmatrix.sync.aligned.m8n8.x4.shared.b16 {%0,%1,%2,%3}, [%4];"
                 : "=r"(r[0]), "=r"(r[1]), "=r"(r[2]), "=r"(r[3]) : "r"(a));
}
__device__ __forceinline__ void ldsm_x2t(uint32_t* r, uint32_t a) {
    asm volatile("ldmatrix.sync.aligned.m8n8.x2.trans.shared.b16 {%0,%1}, [%2];"
                 : "=r"(r[0]), "=r"(r[1]) : "r"(a));
}
__device__ __forceinline__ void mma_bf16(float* c, const uint32_t* a, const uint32_t* b) {
    asm volatile("mma.sync.aligned.m16n8k16.row.col.f32.bf16.bf16.f32 "
                 "{%0,%1,%2,%3}, {%4,%5,%6,%7}, {%8,%9}, {%0,%1,%2,%3};"
                 : "+f"(c[0]), "+f"(c[1]), "+f"(c[2]), "+f"(c[3])
                 : "r"(a[0]), "r"(a[1]), "r"(a[2]), "r"(a[3]), "r"(b[0]), "r"(b[1]));
}
__device__ __forceinline__ uint32_t pack2(__nv_bfloat16 a, __nv_bfloat16 b) {
    return (uint32_t)__bfloat16_as_ushort(a) | ((uint32_t)__bfloat16_as_ushort(b) << 16);
}
__device__ __forceinline__ float2 unpack2(uint32_t u) {
    __nv_bfloat162 t = *reinterpret_cast<__nv_bfloat162*>(&u);
    return __bfloat1622float2(t);
}
// split float4 into 4 bf16 hi + 4 bf16 lo, packed as uint2 each
__device__ __forceinline__ void cvt2(float4 v, uint2& hi, uint2& lo) {
    __nv_bfloat16 hx = __float2bfloat16(v.x), hy = __float2bfloat16(v.y);
    __nv_bfloat16 hz = __float2bfloat16(v.z), hw = __float2bfloat16(v.w);
    hi.x = pack2(hx, hy); hi.y = pack2(hz, hw);
    lo.x = pack2(__float2bfloat16(v.x - __bfloat162float(hx)),
                 __float2bfloat16(v.y - __bfloat162float(hy)));
    lo.y = pack2(__float2bfloat16(v.z - __bfloat162float(hz)),
                 __float2bfloat16(v.w - __bfloat162float(hw)));
}
__device__ __forceinline__ float warp_sum_f(float v) {
#pragma unroll
    for (int o = 16; o > 0; o >>= 1) v += __shfl_xor_sync(0xffffffffu, v, o);
    return v;
}
__device__ __forceinline__ int warp_sum_i(int v) {
#pragma unroll
    for (int o = 16; o > 0; o >>= 1) v += __shfl_xor_sync(0xffffffffu, v, o);
    return v;
}

__global__ void __launch_bounds__(NT, 2)
spattn(const float* __restrict__ Q, const float* __restrict__ K,
       const float* __restrict__ V, float* __restrict__ O)
{
    extern __shared__ char sm[];
    const uint32_t sb0 = smem_u32(sm);
    const int tid = threadIdx.x, lane = tid & 31, w = tid >> 5;
    const int lt = blockIdx.x, h = blockIdx.y, b = blockIdx.z;
    const int l0 = lt * MR;

    // ---------------- Q planes (16 x 64, split bf16) ----------------
    {
        int row = tid >> 4, e4 = tid & 15;
        float4 q = reinterpret_cast<const float4*>(Q)
            [((size_t)(b * L_ + l0 + row) * H_ + h) * 16 + e4];
        uint2 hi, lo; cvt2(q, hi, lo);
        *reinterpret_cast<uint2*>(sm + QHI + row * KVP + e4 * 8) = hi;
        *reinterpret_cast<uint2*>(sm + QLO + row * KVP + e4 * 8) = lo;
    }
    __syncthreads();

    // Q fragments (held across phase 1): a-frag per k16 step, hi & lo
    uint32_t qh[4][4], ql[4][4];
    {
        uint32_t base = sb0 + QHI + (lane & 15) * KVP + ((lane >> 4) << 4);
#pragma unroll
        for (int ks = 0; ks < 4; ++ks) {
            ldsm_x4(qh[ks], base + ks * 32);
            ldsm_x4(ql[ks], base + ks * 32 + (QLO - QHI));
        }
    }

    // ---------------- phase 1: scores = 0.125 * Q K^T ----------------
    // warp w covers s-cols [16w, 16w+16) of each 128-s block (2 n8 tiles)
    for (int ch = 0; ch < S_ / SB; ++ch) {
        const int s0 = ch * SB;
        __syncthreads();                         // W region free
#pragma unroll
        for (int i = 0; i < 8; ++i) {            // K block: 128 s x 64 e fp32
            int idx = tid + i * NT;
            int srow = idx >> 4, e4 = idx & 15;
            float4 kv = reinterpret_cast<const float4*>(K)
                [((size_t)(b * S_ + s0 + srow) * H_ + h) * 16 + e4];
            uint2 hi, lo; cvt2(kv, hi, lo);
            *reinterpret_cast<uint2*>(sm + WREG + srow * KVP + e4 * 8) = hi;
            *reinterpret_cast<uint2*>(sm + WREG + WPL + srow * KVP + e4 * 8) = lo;
        }
        __syncthreads();

        float c0[4] = {0.f, 0.f, 0.f, 0.f}, c1[4] = {0.f, 0.f, 0.f, 0.f};
        uint32_t bBase = sb0 + WREG +
            (w * 16 + ((lane >> 4) << 3) + (lane & 7)) * KVP + ((lane & 8) ? 16 : 0);
#pragma unroll
        for (int ks = 0; ks < 4; ++ks) {
            uint32_t bh[4], bl[4];
            ldsm_x4(bh, bBase + ks * 32);
            ldsm_x4(bl, bBase + ks * 32 + WPL);
            mma_bf16(c0, qh[ks], bh);     mma_bf16(c1, qh[ks], bh + 2);
            mma_bf16(c0, qh[ks], bl);     mma_bf16(c1, qh[ks], bl + 2);
            mma_bf16(c0, ql[ks], bh);     mma_bf16(c1, ql[ks], bh + 2);
        }
        // epilogue: scale, split, store to score planes
        {
            int r = lane >> 2;
            int sc = s0 + w * 16 + (lane & 3) * 2;
#pragma unroll
            for (int f = 0; f < 2; ++f) {
                const float* c = f ? c1 : c0;
                int s = sc + f * 8;
#pragma unroll
                for (int half = 0; half < 2; ++half) {
                    float a = c[2 * half + 0] * 0.125f;
                    float bb = c[2 * half + 1] * 0.125f;
                    __nv_bfloat16 ah = __float2bfloat16(a), bh2 = __float2bfloat16(bb);
                    int row = r + half * 8;
                    *reinterpret_cast<uint32_t*>(sm + AHI + row * APITCH + s * 2) =
                        pack2(ah, bh2);
                    *reinterpret_cast<uint32_t*>(sm + ALO + row * APITCH + s * 2) =
                        pack2(__float2bfloat16(a - __bfloat162float(ah)),
                              __float2bfloat16(bb - __bfloat162float(bh2)));
                }
            }
        }
    }
    __syncthreads();

    // ---------------- phase 2: sparsemax (Michelot, exact) ----------------
    // warp w owns rows 2w, 2w+1; reads z = hi+lo, writes A splits back in place
#pragma unroll
    for (int rr = 0; rr < 2; ++rr) {
        int r = w * 2 + rr;
        char* ph = sm + AHI + r * APITCH;
        char* pl = sm + ALO + r * APITCH;
        float z[32];
#pragma unroll
        for (int k = 0; k < 8; ++k) {
            uint2 hw = *reinterpret_cast<uint2*>(ph + 8 * lane + 256 * k);
            uint2 lw = *reinterpret_cast<uint2*>(pl + 8 * lane + 256 * k);
            float2 h0 = unpack2(hw.x), h1 = unpack2(hw.y);
            float2 m0 = unpack2(lw.x), m1 = unpack2(lw.y);
            z[4 * k + 0] = h0.x + m0.x;  z[4 * k + 1] = h0.y + m0.y;
            z[4 * k + 2] = h1.x + m1.x;  z[4 * k + 3] = h1.y + m1.y;
        }
        float s = 0.f;
#pragma unroll
        for (int k = 0; k < 32; k++) s += z[k];
        s = warp_sum_f(s);
        float tau = (s - 1.0f) * (1.0f / (float)S_);
        int prev = S_;
        for (int iter = 0; iter < 64; ++iter) {
            float ss = 0.f; int c = 0;
#pragma unroll
            for (int k = 0; k < 32; k++) {
                float v = z[k];
                if (v > tau) { ss += v; c += 1; }
            }
            ss = warp_sum_f(ss);
            c  = warp_sum_i(c);
            tau = (ss - 1.0f) / (float)c;
            if (c == prev) break;
            prev = c;
        }
#pragma unroll
        for (int k = 0; k < 8; ++k) {
            float a0 = fmaxf(z[4 * k + 0] - tau, 0.f);
            float a1 = fmaxf(z[4 * k + 1] - tau, 0.f);
            float a2 = fmaxf(z[4 * k + 2] - tau, 0.f);
            float a3 = fmaxf(z[4 * k + 3] - tau, 0.f);
            __nv_bfloat16 h0 = __float2bfloat16(a0), h1 = __float2bfloat16(a1);
            __nv_bfloat16 h2 = __float2bfloat16(a2), h3 = __float2bfloat16(a3);
            uint2 hw, lw;
            hw.x = pack2(h0, h1); hw.y = pack2(h2, h3);
            lw.x = pack2(__float2bfloat16(a0 - __bfloat162float(h0)),
                         __float2bfloat16(a1 - __bfloat162float(h1)));
            lw.y = pack2(__float2bfloat16(a2 - __bfloat162float(h2)),
                         __float2bfloat16(a3 - __bfloat162float(h3)));
            *reinterpret_cast<uint2*>(ph + 8 * lane + 256 * k) = hw;
            *reinterpret_cast<uint2*>(pl + 8 * lane + 256 * k) = lw;
        }
    }
    __syncthreads();

    // ---------------- phase 3: O = A V ----------------
    // M=16 (L rows, A operand = A planes), N=64 (d; warp w -> d cols [8w,8w+8)),
    // K=1024 over s.  V stays row-major [s][d] -> B via ldmatrix.x2.trans.
    float oc[4] = {0.f, 0.f, 0.f, 0.f};
    for (int ch = 0; ch < S_ / SB; ++ch) {
        const int s0 = ch * SB;
        __syncthreads();                         // W free (prior ldmatrix done)
#pragma unroll
        for (int i = 0; i < 8; ++i) {            // V block: 128 s x 64 d fp32
            int idx = tid + i * NT;
            int srow = idx >> 4, d4 = idx & 15;
            float4 vv = reinterpret_cast<const float4*>(V)
                [((size_t)(b * S_ + s0 + srow) * H_ + h) * 16 + d4];
            uint2 hi, lo; cvt2(vv, hi, lo);
            *reinterpret_cast<uint2*>(sm + WREG + srow * KVP + d4 * 8) = hi;
            *reinterpret_cast<uint2*>(sm + WREG + WPL + srow * KVP + d4 * 8) = lo;
        }
        __syncthreads();

        uint32_t aBase = sb0 + AHI + (lane & 15) * APITCH + ((lane >> 4) << 4) + s0 * 2;
        uint32_t bBase = sb0 + WREG + (lane & 15) * KVP + w * 16;
#pragma unroll
        for (int ks = 0; ks < 8; ++ks) {
            uint32_t ah[4], al[4], bh[2], bl[2];
            ldsm_x4(ah, aBase + ks * 32);
            ldsm_x4(al, aBase + ks * 32 + (ALO - AHI));
            ldsm_x2t(bh, bBase + ks * 16 * KVP);
            ldsm_x2t(bl, bBase + ks * 16 * KVP + WPL);
            mma_bf16(oc, ah, bh);
            mma_bf16(oc, ah, bl);
            mma_bf16(oc, al, bh);
        }
    }

    // ---------------- write O [b, l, h, d] ----------------
    {
        int row = lane >> 2;
        int d = w * 8 + (lane & 3) * 2;
        *reinterpret_cast<float2*>(
            O + ((size_t)(b * L_ + l0 + row) * H_ + h) * 64 + d) =
            make_float2(oc[0], oc[1]);
        *reinterpret_cast<float2*>(
            O + ((size_t)(b * L_ + l0 + row + 8) * H_ + h) * 64 + d) =
            make_float2(oc[2], oc[3]);
    }
}

extern "C" void kernel_launch(void* const* d_in, const int* in_sizes, int n_in,
                              void* d_out, int out_size) {
    const float* Q = (const float*)d_in[0];   // [B,L,H,E]
    const float* K = (const float*)d_in[1];   // [B,S,H,E]
    const float* V = (const float*)d_in[2];   // [B,S,H,D]
    float* O = (float*)d_out;                 // [B,L,H,D]

    cudaFuncSetAttribute(spattn, cudaFuncAttributeMaxDynamicSharedMemorySize, SMEM_BYTES);
    dim3 grid(L_ / MR, H_, B_);
    spattn<<<grid, NT, SMEM_BYTES>>>(Q, K, V, O);
}